// round 1
// baseline (speedup 1.0000x reference)
#include <cuda_runtime.h>

// Problem constants (fixed by the dataset): x is (B=8, C=64, H=512, W=512) fp32,
// indices = 32 int32 channel ids, k = 3.
#define B_ 8
#define C_ 64
#define H_ 512
#define W_ 512
#define MAXV 10000.0f

__device__ unsigned char g_chan_mask[C_];

// One block, 64 threads: zero the mask then set bits for the 32 indexed channels.
__global__ void build_mask_kernel(const int* __restrict__ indices, int n_idx) {
    int t = threadIdx.x;
    if (t < C_) g_chan_mask[t] = 0;
    __syncthreads();
    if (t < n_idx) {
        int c = indices[t];
        if (c >= 0 && c < C_) g_chan_mask[c] = 1;
    }
}

// Each thread produces 4 consecutive outputs (one float4).
__global__ void __launch_bounds__(256) erode_copy_kernel(
    const float* __restrict__ x, float* __restrict__ out, int total4) {
    int i = blockIdx.x * blockDim.x + threadIdx.x;
    if (i >= total4) return;

    const int HW4 = (H_ * W_) / 4;           // 65536
    int plane = i / HW4;                      // b*C + c
    int c = plane & (C_ - 1);                 // C = 64
    int p = i - plane * HW4;

    const float4* __restrict__ x4 = (const float4*)x;
    float4* __restrict__ o4 = (float4*)out;

    if (!g_chan_mask[c]) {
        // pass-through copy
        o4[i] = x4[i];
        return;
    }

    int h  = p >> 7;                          // W/4 = 128
    int w4 = p & 127;
    int w  = w4 << 2;

    const float* __restrict__ base =
        x + (size_t)plane * (H_ * W_) + (size_t)h * W_ + w;

    bool has_left  = (w > 0);
    bool has_right = (w + 4 < W_);

    // vertical min over up to 3 rows, 6 columns [w-1 .. w+4]
    float v0, v1, v2, v3, v4, v5;
    {
        float4 m = *(const float4*)base;
        v0 = has_left  ? base[-1] : MAXV;
        v1 = m.x; v2 = m.y; v3 = m.z; v4 = m.w;
        v5 = has_right ? base[4]  : MAXV;
    }
    if (h > 0) {
        const float* r = base - W_;
        float4 t = *(const float4*)r;
        v0 = fminf(v0, has_left  ? r[-1] : MAXV);
        v1 = fminf(v1, t.x);
        v2 = fminf(v2, t.y);
        v3 = fminf(v3, t.z);
        v4 = fminf(v4, t.w);
        v5 = fminf(v5, has_right ? r[4]  : MAXV);
    }
    if (h < H_ - 1) {
        const float* r = base + W_;
        float4 t = *(const float4*)r;
        v0 = fminf(v0, has_left  ? r[-1] : MAXV);
        v1 = fminf(v1, t.x);
        v2 = fminf(v2, t.y);
        v3 = fminf(v3, t.z);
        v4 = fminf(v4, t.w);
        v5 = fminf(v5, has_right ? r[4]  : MAXV);
    }

    float4 o;
    o.x = fminf(fminf(v0, v1), v2);
    o.y = fminf(fminf(v1, v2), v3);
    o.z = fminf(fminf(v2, v3), v4);
    o.w = fminf(fminf(v3, v4), v5);
    o4[i] = o;
}

extern "C" void kernel_launch(void* const* d_in, const int* in_sizes, int n_in,
                              void* d_out, int out_size) {
    const float* x       = (const float*)d_in[0];
    const int*   indices = (const int*)d_in[1];
    int n_idx = in_sizes[1];
    float* out = (float*)d_out;

    build_mask_kernel<<<1, 64>>>(indices, n_idx);

    int total4 = out_size / 4;                 // 33,554,432
    int blocks = (total4 + 255) / 256;
    erode_copy_kernel<<<blocks, 256>>>(x, out, total4);
}